// round 6
// baseline (speedup 1.0000x reference)
#include <cuda_runtime.h>
#include <math.h>

#define B_    2
#define N_    8
#define K_    8
#define C_    256
#define HW_   9216
#define BN_   16
#define TILES_ 36            // HW / 256 pixels per tile
#define TPX_  256            // pixels per tile (1 per thread)
#define NPART_ (TILES_ * 8)  // 288 per-warp partials

// ---------------- scratch (__device__ globals: no allocation allowed) -------
__device__ float d_wpart[NPART_ * BN_ * C_];  // per-warp partial sum(v*m)
__device__ float d_vpart[NPART_ * BN_ * C_];  // per-warp partial sum(v)
__device__ float d_mpart[NPART_ * BN_];       // per-warp partial sum(m)
__device__ float d_maxes[2];                  // global age max, usage max
__device__ float d_validf[BN_ * K_];          // decoded valid flags
__device__ float d_pnew[BN_ * K_ * C_];       // proto_new
__device__ float d_bnn [BN_ * K_ * C_];       // l2norm(proto_new)
__device__ float d_vldn[BN_ * K_];            // valid_new
__device__ int   d_anyv[BN_], d_upd[BN_], d_mode[BN_];
__device__ float d_rsim[BN_ * K_ * HW_];      // pre-policy rsim (old protos)
__device__ float d_invn[BN_ * HW_];           // 1/||value(:,pix)||

__device__ __forceinline__ float warpSum(float v) {
    #pragma unroll
    for (int o = 16; o; o >>= 1) v += __shfl_xor_sync(0xffffffffu, v, o);
    return v;
}
__device__ __forceinline__ float warpMax(float v) {
    #pragma unroll
    for (int o = 16; o; o >>= 1) v = fmaxf(v, __shfl_xor_sync(0xffffffffu, v, o));
    return v;
}

// ---------------- kernel 0: valid decode (dtype sniff) + age/usage maxes ----
__global__ void k_small(const void* __restrict__ valid,
                        const float* __restrict__ age,
                        const float* __restrict__ usage) {
    int t = threadIdx.x;                 // 128 threads
    __shared__ int s_mode;
    if (t == 0) {
        const unsigned int* w = (const unsigned int*)valid;
        int isInt = 1, isFlt = 1;
        for (int i = 0; i < 32; i++) {
            unsigned int x = w[i];
            isInt &= (x <= 1u);
            isFlt &= (x == 0u || x == 0x3f800000u);
        }
        s_mode = isInt ? 1 : (isFlt ? 2 : 0);
    }
    __syncthreads();
    int v;
    if (s_mode == 1)      v = ((const int*)valid)[t] != 0;
    else if (s_mode == 2) v = ((const float*)valid)[t] != 0.0f;
    else                  v = ((const unsigned char*)valid)[t] != 0;
    d_validf[t] = v ? 1.0f : 0.0f;

    float a = warpMax(age[t]), u = warpMax(usage[t]);
    __shared__ float sa[4], su[4];
    if ((t & 31) == 0) { sa[t >> 5] = a; su[t >> 5] = u; }
    __syncthreads();
    if (t == 0) {
        float A = sa[0], U = su[0];
        #pragma unroll
        for (int i = 1; i < 4; i++) { A = fmaxf(A, sa[i]); U = fmaxf(U, su[i]); }
        d_maxes[0] = A; d_maxes[1] = U;
    }
}

// ---------------- kernel F1: fused candsum + pre-policy rsim ----------------
// grid (36, N, B), 256 threads, 1 pixel each. Single full read of value.
__global__ void __launch_bounds__(256) k_f1(const float* __restrict__ value,
                                            const float* __restrict__ mask,
                                            const float* __restrict__ proto) {
    int tile = blockIdx.x;
    int bn   = blockIdx.z * N_ + blockIdx.y;
    int t = threadIdx.x, w = t >> 5, l = t & 31;
    __shared__ float s_pnT[C_][K_];     // l2norm(proto) transposed: [c][k]

    // normalize proto: warp w owns slot w
    {
        const float* pb = proto + ((size_t)bn * K_ + w) * C_;
        float pr[8]; float ps = 0.f;
        #pragma unroll
        for (int i = 0; i < 8; i++) { pr[i] = pb[i * 32 + l]; ps += pr[i] * pr[i]; }
        ps = warpSum(ps);
        float inv = 1.0f / fmaxf(sqrtf(ps), 1e-12f);
        #pragma unroll
        for (int i = 0; i < 8; i++) s_pnT[i * 32 + l][w] = pr[i] * inv;
    }
    __syncthreads();

    int pix = tile * TPX_ + t;
    float m = mask[(size_t)bn * HW_ + pix];
    {   // mask partial (one float per warp)
        float ms = warpSum(m);
        if (l == 0) d_mpart[(tile * 8 + w) * BN_ + bn] = ms;
    }

    const float* vb = value + (size_t)bn * C_ * HW_ + pix;
    float* wp = &d_wpart[((size_t)(tile * 8 + w) * BN_ + bn) * C_];
    float* vp = &d_vpart[((size_t)(tile * 8 + w) * BN_ + bn) * C_];

    float r[K_];
    #pragma unroll
    for (int k = 0; k < K_; k++) r[k] = 0.f;
    float ns = 0.f;

    #pragma unroll 4
    for (int c = 0; c < C_; c++) {
        float v = vb[(size_t)c * HW_];
        ns += v * v;
        float4 p0 = *(const float4*)&s_pnT[c][0];
        float4 p1 = *(const float4*)&s_pnT[c][4];
        r[0] += p0.x * v; r[1] += p0.y * v; r[2] += p0.z * v; r[3] += p0.w * v;
        r[4] += p1.x * v; r[5] += p1.y * v; r[6] += p1.z * v; r[7] += p1.w * v;
        float ws = warpSum(v * m);
        float vs = warpSum(v);
        if (l == 0) { wp[c] = ws; vp[c] = vs; }
    }

    float inv = 1.0f / fmaxf(sqrtf(ns), 1e-12f);
    d_invn[(size_t)bn * HW_ + pix] = inv;
    #pragma unroll
    for (int k = 0; k < K_; k++)
        d_rsim[((size_t)bn * K_ + k) * HW_ + pix] = r[k] * inv;
}

// ---------------- kernel: policy + bank update ------------------------------
// One block per (b,n), 256 threads (8 warps, warp k handles sim for slot k).
__global__ void __launch_bounds__(256) k_policy(const float* __restrict__ proto,
                                                const float* __restrict__ age,
                                                const float* __restrict__ usage,
                                                const float* __restrict__ conf) {
    int bn = blockIdx.x, t = threadIdx.x;
    __shared__ float s_cand[C_], s_sim[K_], s_red[8];
    __shared__ float s_msum;
    __shared__ int s_updS, s_modeS;

    // msum = sum of 288 warp partials
    {
        float ms = 0.f;
        for (int p = t; p < NPART_; p += 256) ms += d_mpart[p * BN_ + bn];
        ms = warpSum(ms);
        if ((t & 31) == 0) s_red[t >> 5] = ms;
        __syncthreads();
        if (t == 0) {
            float r = 0.f;
            #pragma unroll
            for (int i = 0; i < 8; i++) r += s_red[i];
            s_msum = r;
        }
        __syncthreads();
    }

    // candidate prototype (channel t), l2-normalized
    float wsum = 0.f, vsum = 0.f;
    for (int p = 0; p < NPART_; p++) {
        wsum += d_wpart[((size_t)p * BN_ + bn) * C_ + t];
        vsum += d_vpart[((size_t)p * BN_ + bn) * C_ + t];
    }
    float msum = s_msum;
    float cc = (msum <= 1e-5f) ? vsum * (1.0f / (float)HW_)
                               : wsum / fmaxf(msum, 1e-6f);
    float ss = warpSum(cc * cc);
    if ((t & 31) == 0) s_red[t >> 5] = ss;
    __syncthreads();
    float tot = 0.f;
    #pragma unroll
    for (int i = 0; i < 8; i++) tot += s_red[i];
    float cn = cc / fmaxf(sqrtf(tot), 1e-12f);
    s_cand[t] = cn;
    __syncthreads();

    // sim[k] = dot(cand_n, l2norm(proto_k)), -1 if invalid (warp k)
    int w = t >> 5, l = t & 31;
    const float* pbase = proto + (size_t)bn * K_ * C_;
    {
        float ps = 0.f, pd = 0.f;
        #pragma unroll
        for (int i = 0; i < 8; i++) {
            float p = pbase[w * C_ + i * 32 + l];
            ps += p * p;
            pd += p * s_cand[i * 32 + l];
        }
        ps = warpSum(ps); pd = warpSum(pd);
        if (l == 0) {
            float sim = pd / fmaxf(sqrtf(ps), 1e-12f);
            s_sim[w] = (d_validf[bn * K_ + w] > 0.5f) ? sim : -1.0f;
        }
    }
    __syncthreads();

    if (t == 0) {
        bool v[K_]; bool anyv = false, anyi = false;
        #pragma unroll
        for (int k = 0; k < K_; k++) {
            v[k] = (d_validf[bn * K_ + k] > 0.5f);
            anyv |= v[k]; anyi |= !v[k];
        }
        float best = -1e30f; int tgt = 0;
        #pragma unroll
        for (int k = 0; k < K_; k++) if (s_sim[k] > best) { best = s_sim[k]; tgt = k; }
        int target = anyv ? tgt : 0;
        float msim = anyv ? s_sim[target] : -1.0f;
        // A_KEEP=0, A_REFINE=1, A_SPAWN=3
        int action = (!anyv) ? 3 : ((msim >= 0.8f) ? 1 : ((msim >= 0.3f) ? 0 : 3));
        float am = fmaxf(d_maxes[0], 1.0f), um = fmaxf(d_maxes[1], 1.0f);
        float bs = -1e30f; int vic = 0;
        #pragma unroll
        for (int k = 0; k < K_; k++) {
            float sc = age[bn * K_ + k] / am
                     + (1.0f - usage[bn * K_ + k] / um)
                     + (1.0f - conf[bn * K_ + k]);
            if (sc > bs) { bs = sc; vic = k; }
        }
        int fe = 0;
        for (int k = 0; k < K_; k++) { if (!v[k]) { fe = k; break; } }
        int spawn = anyi ? fe : vic;
        int upd = (action == 1) ? target : spawn;
        int mode = (action == 1) ? 1 : ((action == 3) ? 2 : 0);  // 1=refine, 2=spawn
        s_updS = upd; s_modeS = mode;
        d_upd[bn] = upd; d_mode[bn] = mode;
        d_anyv[bn] = (anyv || mode == 2) ? 1 : 0;
    }
    __syncthreads();
    int upd = s_updS, mode = s_modeS;

    // proto_new + bank_nn + valid_new
    for (int k = 0; k < K_; k++) {
        float p = pbase[k * C_ + t];
        float pn = p;
        if (k == upd) {
            if (mode == 1)      pn = 0.7f * p + 0.3f * s_cand[t];
            else if (mode == 2) pn = s_cand[t];
        }
        float q = warpSum(pn * pn);
        __syncthreads();
        if ((t & 31) == 0) s_red[t >> 5] = q;
        __syncthreads();
        float nt = 0.f;
        #pragma unroll
        for (int i = 0; i < 8; i++) nt += s_red[i];
        float inv = 1.0f / fmaxf(sqrtf(nt), 1e-12f);
        float pw = pn;
        if (k == upd && mode == 1) pw = pn * inv;   // refine slot stores normalized
        size_t o = (size_t)bn * K_ * C_ + k * C_ + t;
        d_pnew[o] = pw;
        d_bnn[o]  = pn * inv;
        if (t == 0) {
            bool vk = (d_validf[bn * K_ + k] > 0.5f);
            d_vldn[bn * K_ + k] = (vk || (mode == 2 && k == upd)) ? 1.0f : 0.0f;
        }
    }
}

// ---------------- kernel F2: single-slot rsim fix + softmax + blend ---------
// grid (36, N, B), 256 threads, 1 pixel each.
__global__ void __launch_bounds__(256) k_f2(const float* __restrict__ value,
                                            const float* __restrict__ frame,
                                            const float* __restrict__ pgate,
                                            const float* __restrict__ fgate,
                                            float* __restrict__ out) {
    int tile = blockIdx.x, n = blockIdx.y, b = blockIdx.z;
    int bn = b * N_ + n, t = threadIdx.x;
    __shared__ float s_pnT[C_][K_];     // proto_new transposed
    __shared__ float s_bu[C_];          // l2norm(proto_new)[upd]
    __shared__ float s_vld[K_];
    __shared__ int s_any, s_upd, s_mode;

    const size_t off = (size_t)bn * K_ * C_;
    #pragma unroll
    for (int i = 0; i < 8; i++) s_pnT[t][i] = d_pnew[off + (size_t)i * C_ + t];
    if (t == 0) { s_any = d_anyv[bn]; s_upd = d_upd[bn]; s_mode = d_mode[bn]; }
    if (t < K_) s_vld[t] = d_vldn[bn * K_ + t];
    __syncthreads();
    s_bu[t] = d_bnn[off + (size_t)s_upd * C_ + t];
    int mode = s_mode, upd = s_upd, any = s_any;
    __syncthreads();

    int pix = tile * TPX_ + t;
    float s[K_];
    #pragma unroll
    for (int k = 0; k < K_; k++) s[k] = d_rsim[((size_t)bn * K_ + k) * HW_ + pix];

    const float* vb = value + (size_t)bn * C_ * HW_ + pix;
    if (mode != 0) {
        float cd = 0.f;
        #pragma unroll 8
        for (int c = 0; c < C_; c++) cd += s_bu[c] * vb[(size_t)c * HW_];
        float corr = cd * d_invn[(size_t)bn * HW_ + pix];
        #pragma unroll
        for (int k = 0; k < K_; k++) if (k == upd) s[k] = corr;
    }

    float a[K_];
    if (!any) {
        #pragma unroll
        for (int k = 0; k < K_; k++) a[k] = 0.f;
    } else {
        float m = -1e30f;
        #pragma unroll
        for (int k = 0; k < K_; k++) if (s_vld[k] > 0.5f) m = fmaxf(m, s[k]);
        float tot = 0.f;
        #pragma unroll
        for (int k = 0; k < K_; k++) {
            float e = (s_vld[k] > 0.5f) ? __expf(s[k] - m) : 0.f;
            a[k] = e; tot += e;
        }
        float z = 1.0f / tot;
        #pragma unroll
        for (int k = 0; k < K_; k++) a[k] *= z;
    }

    float pg = *pgate, fg = *fgate;
    const float* fb = frame + (size_t)b * C_ * HW_ + pix;
    float* ob = out + (size_t)bn * C_ * HW_ + pix;
    #pragma unroll 4
    for (int c = 0; c < C_; c++) {
        float v = vb[(size_t)c * HW_];
        float f = fb[(size_t)c * HW_];
        float4 p0 = *(const float4*)&s_pnT[c][0];
        float4 p1 = *(const float4*)&s_pnT[c][4];
        float pm = a[0] * p0.x + a[1] * p0.y + a[2] * p0.z + a[3] * p0.w
                 + a[4] * p1.x + a[5] * p1.y + a[6] * p1.z + a[7] * p1.w;
        ob[(size_t)c * HW_] = v + pg * pm + fg * f;
    }
}

// ---------------- launch ----------------------------------------------------
extern "C" void kernel_launch(void* const* d_in, const int* in_sizes, int n_in,
                              void* d_out, int out_size) {
    const float* value = (const float*)d_in[0];
    const float* frame = (const float*)d_in[1];
    const float* mask  = (const float*)d_in[2];
    const float* proto = (const float*)d_in[3];
    const float* age   = (const float*)d_in[4];
    const float* usage = (const float*)d_in[5];
    const float* conf  = (const float*)d_in[6];
    // d_in[7..10] = W1, b1, W2, b2: dead code (logits unused by the output)
    const float* pgate = (const float*)d_in[11];
    const float* fgate = (const float*)d_in[12];
    const void*  valid = (const void*)d_in[13];
    float* out = (float*)d_out;

    k_small<<<1, 128>>>(valid, age, usage);
    dim3 g(TILES_, N_, B_);
    k_f1<<<g, 256>>>(value, mask, proto);
    k_policy<<<BN_, 256>>>(proto, age, usage, conf);
    k_f2<<<g, 256>>>(value, frame, pgate, fgate, out);
}

// round 7
// speedup vs baseline: 1.5725x; 1.5725x over previous
#include <cuda_runtime.h>
#include <math.h>

#define B_  2
#define N_  8
#define K_  8
#define C_  256
#define HW_ 9216
#define BN_ (B_*N_)

// ---------------- scratch (__device__ globals: no allocation allowed) -------
__device__ float d_wsum[BN_*C_];     // sum(value*mask) over HW
__device__ float d_vsum[BN_*C_];     // sum(value) over HW
__device__ float d_msum[BN_];        // sum(mask) over HW
__device__ float d_maxes[2];         // global age max, usage max
__device__ float d_validf[BN_*K_];   // decoded `valid` (dtype-sniffed)
__device__ float d_pnew[BN_*K_*C_];  // proto_new
__device__ float d_bnn [BN_*K_*C_];  // l2norm(proto_new)
__device__ float d_vldn[BN_*K_];     // valid_new as float
__device__ int   d_anyv[BN_];        // any(valid_new)

__device__ __forceinline__ float warpSum(float v) {
    #pragma unroll
    for (int o = 16; o; o >>= 1) v += __shfl_xor_sync(0xffffffffu, v, o);
    return v;
}
__device__ __forceinline__ float warpMax(float v) {
    #pragma unroll
    for (int o = 16; o; o >>= 1) v = fmaxf(v, __shfl_xor_sync(0xffffffffu, v, o));
    return v;
}

// ---------------- kernel 0: valid decode (dtype sniff) + age/usage maxes ----
__global__ void k_small(const void* __restrict__ valid,
                        const float* __restrict__ age,
                        const float* __restrict__ usage) {
    int t = threadIdx.x;                 // 128 threads
    __shared__ int s_mode;
    if (t == 0) {
        const unsigned int* w = (const unsigned int*)valid;
        int isInt = 1, isFlt = 1;
        for (int i = 0; i < 32; i++) {
            unsigned int x = w[i];
            isInt &= (x <= 1u);
            isFlt &= (x == 0u || x == 0x3f800000u);
        }
        s_mode = isInt ? 1 : (isFlt ? 2 : 0);
    }
    __syncthreads();
    int v;
    if (s_mode == 1)      v = ((const int*)valid)[t] != 0;
    else if (s_mode == 2) v = ((const float*)valid)[t] != 0.0f;
    else                  v = ((const unsigned char*)valid)[t] != 0;
    d_validf[t] = v ? 1.0f : 0.0f;

    float a = warpMax(age[t]), u = warpMax(usage[t]);
    __shared__ float sa[4], su[4];
    if ((t & 31) == 0) { sa[t >> 5] = a; su[t >> 5] = u; }
    __syncthreads();
    if (t == 0) {
        float A = sa[0], U = su[0];
        #pragma unroll
        for (int i = 1; i < 4; i++) { A = fmaxf(A, sa[i]); U = fmaxf(U, su[i]); }
        d_maxes[0] = A; d_maxes[1] = U;
    }
}

// ---------------- kernel: sum(mask) per (b,n) -------------------------------
__global__ void k_msum(const float* __restrict__ mask) {
    int bn = blockIdx.x, t = threadIdx.x;                 // 256 threads
    const float4* m4 = (const float4*)(mask + (size_t)bn * HW_);
    float s = 0.f;
    #pragma unroll
    for (int i = 0; i < 9; i++) {                          // 9216/4/256 = 9
        float4 m = m4[i * 256 + t];
        s += m.x + m.y + m.z + m.w;
    }
    s = warpSum(s);
    __shared__ float sb[8];
    if ((t & 31) == 0) sb[t >> 5] = s;
    __syncthreads();
    if (t == 0) {
        float r = 0.f;
        #pragma unroll
        for (int i = 0; i < 8; i++) r += sb[i];
        d_msum[bn] = r;
    }
}

// ---------------- kernel: masked pooling sums over HW -----------------------
// grid (C, N, B), 256 threads. Reads full value once (151 MB). 66% DRAM in R5.
__global__ void __launch_bounds__(256) k_candsum(const float* __restrict__ value,
                                                 const float* __restrict__ mask) {
    int c  = blockIdx.x;
    int bn = blockIdx.z * N_ + blockIdx.y;
    int t  = threadIdx.x;
    const float4* v4 = (const float4*)(value + ((size_t)bn * C_ + c) * HW_);
    const float4* m4 = (const float4*)(mask + (size_t)bn * HW_);
    float ws = 0.f, vs = 0.f;
    #pragma unroll
    for (int i = 0; i < 9; i++) {
        float4 v = v4[i * 256 + t];
        float4 m = m4[i * 256 + t];
        ws += v.x * m.x + v.y * m.y + v.z * m.z + v.w * m.w;
        vs += v.x + v.y + v.z + v.w;
    }
    ws = warpSum(ws); vs = warpSum(vs);
    __shared__ float sw[8], sv[8];
    if ((t & 31) == 0) { sw[t >> 5] = ws; sv[t >> 5] = vs; }
    __syncthreads();
    if (t == 0) {
        float a = 0.f, b = 0.f;
        #pragma unroll
        for (int i = 0; i < 8; i++) { a += sw[i]; b += sv[i]; }
        d_wsum[bn * C_ + c] = a;
        d_vsum[bn * C_ + c] = b;
    }
}

// ---------------- kernel: policy + bank update ------------------------------
__global__ void __launch_bounds__(256) k_policy(const float* __restrict__ proto,
                                                const float* __restrict__ age,
                                                const float* __restrict__ usage,
                                                const float* __restrict__ conf) {
    int bn = blockIdx.x, t = threadIdx.x;
    __shared__ float s_cand[C_], s_sim[K_], s_red[8];
    __shared__ int s_upd, s_mode;

    // candidate prototype (raw), then l2-normalize
    float msum = d_msum[bn];
    float cc = (msum <= 1e-5f)
             ? d_vsum[bn * C_ + t] * (1.0f / (float)HW_)
             : d_wsum[bn * C_ + t] / fmaxf(msum, 1e-6f);
    float ss = warpSum(cc * cc);
    if ((t & 31) == 0) s_red[t >> 5] = ss;
    __syncthreads();
    float tot = 0.f;
    #pragma unroll
    for (int i = 0; i < 8; i++) tot += s_red[i];
    float cn = cc / fmaxf(sqrtf(tot), 1e-12f);
    s_cand[t] = cn;
    __syncthreads();

    // sim[k] = dot(cand_n, l2norm(proto_k)), -1 if invalid (warp k)
    int w = t >> 5, l = t & 31;
    const float* pbase = proto + (size_t)bn * K_ * C_;
    {
        float ps = 0.f, pd = 0.f;
        #pragma unroll
        for (int i = 0; i < 8; i++) {
            float p = pbase[w * C_ + i * 32 + l];
            ps += p * p;
            pd += p * s_cand[i * 32 + l];
        }
        ps = warpSum(ps); pd = warpSum(pd);
        if (l == 0) {
            float sim = pd / fmaxf(sqrtf(ps), 1e-12f);
            s_sim[w] = (d_validf[bn * K_ + w] > 0.5f) ? sim : -1.0f;
        }
    }
    __syncthreads();

    if (t == 0) {
        bool v[K_]; bool anyv = false, anyi = false;
        #pragma unroll
        for (int k = 0; k < K_; k++) {
            v[k] = (d_validf[bn * K_ + k] > 0.5f);
            anyv |= v[k]; anyi |= !v[k];
        }
        float best = -1e30f; int tgt = 0;
        #pragma unroll
        for (int k = 0; k < K_; k++) if (s_sim[k] > best) { best = s_sim[k]; tgt = k; }
        int target = anyv ? tgt : 0;
        float msim = anyv ? s_sim[target] : -1.0f;
        // A_KEEP=0, A_REFINE=1, A_SPAWN=3
        int action = (!anyv) ? 3 : ((msim >= 0.8f) ? 1 : ((msim >= 0.3f) ? 0 : 3));
        float am = fmaxf(d_maxes[0], 1.0f), um = fmaxf(d_maxes[1], 1.0f);
        float bs = -1e30f; int vic = 0;
        #pragma unroll
        for (int k = 0; k < K_; k++) {
            float sc = age[bn * K_ + k] / am
                     + (1.0f - usage[bn * K_ + k] / um)
                     + (1.0f - conf[bn * K_ + k]);
            if (sc > bs) { bs = sc; vic = k; }
        }
        int fe = 0;
        for (int k = 0; k < K_; k++) { if (!v[k]) { fe = k; break; } }
        int spawn = anyi ? fe : vic;
        int upd = (action == 1) ? target : spawn;
        int mode = (action == 1) ? 1 : ((action == 3) ? 2 : 0);  // 1=refine, 2=spawn
        s_upd = upd; s_mode = mode;
        d_anyv[bn] = (anyv || mode == 2) ? 1 : 0;
    }
    __syncthreads();
    int upd = s_upd, mode = s_mode;

    // proto_new + bank_nn + valid_new
    for (int k = 0; k < K_; k++) {
        float p = pbase[k * C_ + t];
        float pn = p;
        if (k == upd) {
            if (mode == 1)      pn = 0.7f * p + 0.3f * s_cand[t];
            else if (mode == 2) pn = s_cand[t];
        }
        float q = warpSum(pn * pn);
        __syncthreads();                     // protect s_red reuse
        if ((t & 31) == 0) s_red[t >> 5] = q;
        __syncthreads();
        float nt = 0.f;
        #pragma unroll
        for (int i = 0; i < 8; i++) nt += s_red[i];
        float inv = 1.0f / fmaxf(sqrtf(nt), 1e-12f);
        float pw = pn;
        if (k == upd && mode == 1) pw = pn * inv;   // refine slot stores normalized
        size_t o = (size_t)bn * K_ * C_ + k * C_ + t;
        d_pnew[o] = pw;
        d_bnn[o]  = pn * inv;
        if (t == 0) {
            bool vk = (d_validf[bn * K_ + k] > 0.5f);
            d_vldn[bn * K_ + k] = (vk || (mode == 2 && k == upd)) ? 1.0f : 0.0f;
        }
    }
}

// ---------------- kernel: readout + output blend ----------------------------
// grid (9, N, B) = 144 blocks, 512 threads, 2 pixels per thread (float2).
// Scans batch 8 channel-loads into registers before math (MLP ~= 8).
__global__ void __launch_bounds__(512) k_readout(const float* __restrict__ value,
                                                 const float* __restrict__ frame,
                                                 const float* __restrict__ pgate,
                                                 const float* __restrict__ fgate,
                                                 float* __restrict__ out) {
    int tile = blockIdx.x, n = blockIdx.y, b = blockIdx.z;
    int bn = b * N_ + n;
    int t = threadIdx.x;
    __shared__ float s_bnnT[C_][K_];   // l2norm(proto_new) transposed [c][k]
    __shared__ float s_pnT [C_][K_];   // proto_new transposed [c][k]
    __shared__ float s_vld[K_];
    __shared__ int s_any;
    const size_t off = (size_t)bn * K_ * C_;
    #pragma unroll
    for (int i = 0; i < 4; i++) {
        int j = i * 512 + t;           // j = k*C + c
        int k = j >> 8, c = j & 255;
        s_bnnT[c][k] = d_bnn[off + j];
        s_pnT [c][k] = d_pnew[off + j];
    }
    if (t < K_) s_vld[t] = d_vldn[bn * K_ + t];
    if (t == 0) s_any = d_anyv[bn];
    __syncthreads();

    int pix = tile * 1024 + t * 2;
    const float* vb = value + (size_t)bn * C_ * HW_ + pix;

    // ---- scan 1: rsim + ||v|| ----
    float ns0 = 0.f, ns1 = 0.f;
    float r0[K_], r1[K_];
    #pragma unroll
    for (int k = 0; k < K_; k++) { r0[k] = 0.f; r1[k] = 0.f; }

    for (int cb = 0; cb < C_; cb += 8) {
        float2 v[8];
        #pragma unroll
        for (int i = 0; i < 8; i++)
            v[i] = *(const float2*)(vb + (size_t)(cb + i) * HW_);
        #pragma unroll
        for (int i = 0; i < 8; i++) {
            ns0 += v[i].x * v[i].x; ns1 += v[i].y * v[i].y;
            float4 p0 = *(const float4*)&s_bnnT[cb + i][0];
            float4 p1 = *(const float4*)&s_bnnT[cb + i][4];
            r0[0] += p0.x * v[i].x; r1[0] += p0.x * v[i].y;
            r0[1] += p0.y * v[i].x; r1[1] += p0.y * v[i].y;
            r0[2] += p0.z * v[i].x; r1[2] += p0.z * v[i].y;
            r0[3] += p0.w * v[i].x; r1[3] += p0.w * v[i].y;
            r0[4] += p1.x * v[i].x; r1[4] += p1.x * v[i].y;
            r0[5] += p1.y * v[i].x; r1[5] += p1.y * v[i].y;
            r0[6] += p1.z * v[i].x; r1[6] += p1.z * v[i].y;
            r0[7] += p1.w * v[i].x; r1[7] += p1.w * v[i].y;
        }
    }
    float i0 = 1.0f / fmaxf(sqrtf(ns0), 1e-12f);
    float i1 = 1.0f / fmaxf(sqrtf(ns1), 1e-12f);

    // ---- softmax over valid slots ----
    float a0[K_], a1[K_];
    if (!s_any) {
        #pragma unroll
        for (int k = 0; k < K_; k++) { a0[k] = 0.f; a1[k] = 0.f; }
    } else {
        float m0 = -1e30f, m1 = -1e30f;
        #pragma unroll
        for (int k = 0; k < K_; k++) {
            if (s_vld[k] > 0.5f) {
                m0 = fmaxf(m0, r0[k] * i0);
                m1 = fmaxf(m1, r1[k] * i1);
            }
        }
        float t0 = 0.f, t1 = 0.f;
        #pragma unroll
        for (int k = 0; k < K_; k++) {
            float e0 = (s_vld[k] > 0.5f) ? __expf(r0[k] * i0 - m0) : 0.f;
            float e1 = (s_vld[k] > 0.5f) ? __expf(r1[k] * i1 - m1) : 0.f;
            a0[k] = e0; a1[k] = e1;
            t0 += e0; t1 += e1;
        }
        float z0 = 1.0f / t0, z1 = 1.0f / t1;
        #pragma unroll
        for (int k = 0; k < K_; k++) { a0[k] *= z0; a1[k] *= z1; }
    }

    // ---- scan 2: blend (value from L2, frame, store) ----
    float pg = *pgate, fg = *fgate;
    const float* fb = frame + (size_t)b * C_ * HW_ + pix;
    float* ob = out + (size_t)bn * C_ * HW_ + pix;
    for (int cb = 0; cb < C_; cb += 8) {
        float2 v[8], f[8];
        #pragma unroll
        for (int i = 0; i < 8; i++) {
            v[i] = *(const float2*)(vb + (size_t)(cb + i) * HW_);
            f[i] = *(const float2*)(fb + (size_t)(cb + i) * HW_);
        }
        #pragma unroll
        for (int i = 0; i < 8; i++) {
            float4 p0 = *(const float4*)&s_pnT[cb + i][0];
            float4 p1 = *(const float4*)&s_pnT[cb + i][4];
            float pm0 = a0[0] * p0.x + a0[1] * p0.y + a0[2] * p0.z + a0[3] * p0.w
                      + a0[4] * p1.x + a0[5] * p1.y + a0[6] * p1.z + a0[7] * p1.w;
            float pm1 = a1[0] * p0.x + a1[1] * p0.y + a1[2] * p0.z + a1[3] * p0.w
                      + a1[4] * p1.x + a1[5] * p1.y + a1[6] * p1.z + a1[7] * p1.w;
            float2 o;
            o.x = v[i].x + pg * pm0 + fg * f[i].x;
            o.y = v[i].y + pg * pm1 + fg * f[i].y;
            *(float2*)(ob + (size_t)(cb + i) * HW_) = o;
        }
    }
}

// ---------------- launch ----------------------------------------------------
extern "C" void kernel_launch(void* const* d_in, const int* in_sizes, int n_in,
                              void* d_out, int out_size) {
    const float* value = (const float*)d_in[0];
    const float* frame = (const float*)d_in[1];
    const float* mask  = (const float*)d_in[2];
    const float* proto = (const float*)d_in[3];
    const float* age   = (const float*)d_in[4];
    const float* usage = (const float*)d_in[5];
    const float* conf  = (const float*)d_in[6];
    // d_in[7..10] = W1, b1, W2, b2: dead code (logits unused by the output)
    const float* pgate = (const float*)d_in[11];
    const float* fgate = (const float*)d_in[12];
    const void*  valid = (const void*)d_in[13];
    float* out = (float*)d_out;

    k_small<<<1, 128>>>(valid, age, usage);
    k_msum<<<BN_, 256>>>(mask);
    dim3 gc(C_, N_, B_);
    k_candsum<<<gc, 256>>>(value, mask);
    k_policy<<<BN_, 256>>>(proto, age, usage, conf);
    dim3 gr(HW_ / 1024, N_, B_);
    k_readout<<<gr, 512>>>(value, frame, pgate, fgate, out);
}